// round 2
// baseline (speedup 1.0000x reference)
#include <cuda_runtime.h>
#include <cuda_bf16.h>
#include <cstdint>

// Problem sizes
#define TOK   16384      // B*S tokens
#define DDIM  768
#define FDIM  3072
#define NEXP  8
#define BM    128
#define BN    128
#define BK    8
#define MAXTILES 136               // TOK/BM + NEXP padding tiles
#define PADT  (MAXTILES * BM)      // 17408 padded rows
#define OUT0  ((size_t)TOK * DDIM) // 12,582,912  (out region)
#define OUT1  (OUT0 + (size_t)TOK * NEXP)  // logits region end -> index region

// ---------------- scratch (device globals; no allocations allowed) ----------
__device__ float g_top_prob[TOK];
__device__ int   g_expert[TOK];
__device__ int   g_counts[NEXP];
__device__ int   g_counts2[NEXP];
__device__ int   g_padoff[NEXP];
__device__ int   g_ntiles;
__device__ int   g_perm[PADT];
__device__ int   g_tile_expert[MAXTILES];
__device__ float g_hidden[(size_t)PADT * FDIM];   // ~214 MB intermediate

// ---------------- kernel 0: reset counters ----------------------------------
__global__ void reset_kernel() {
    int t = threadIdx.x;
    if (t < NEXP) { g_counts[t] = 0; g_counts2[t] = 0; }
}

// ---------------- kernel 1: router (warp per token) --------------------------
__global__ void router_kernel(const float* __restrict__ x,
                              const float* __restrict__ rw,
                              float* __restrict__ out, int aux) {
    int w    = (blockIdx.x * blockDim.x + threadIdx.x) >> 5;
    int lane = threadIdx.x & 31;
    if (w >= TOK) return;
    const float* xr = x + (size_t)w * DDIM;
    float acc[NEXP];
#pragma unroll
    for (int e = 0; e < NEXP; e++) acc[e] = 0.f;
    for (int d = lane; d < DDIM; d += 32) {
        float xv = xr[d];
        const float* r = rw + d * NEXP;
#pragma unroll
        for (int e = 0; e < NEXP; e++) acc[e] = fmaf(xv, r[e], acc[e]);
    }
#pragma unroll
    for (int e = 0; e < NEXP; e++)
#pragma unroll
        for (int o = 16; o; o >>= 1) acc[e] += __shfl_xor_sync(0xffffffffu, acc[e], o);
    if (lane == 0) {
        float m = acc[0]; int be = 0;
#pragma unroll
        for (int e = 1; e < NEXP; e++) if (acc[e] > m) { m = acc[e]; be = e; }
        float s = 0.f;
#pragma unroll
        for (int e = 0; e < NEXP; e++) s += expf(acc[e] - m);
        g_expert[w]   = be;
        g_top_prob[w] = 1.f / s;             // exp(m-m)/sum = top softmax prob
        atomicAdd(&g_counts[be], 1);
        if (aux) {
            float* lg = out + OUT0 + (size_t)w * NEXP;
#pragma unroll
            for (int e = 0; e < NEXP; e++) lg[e] = acc[e];
            out[OUT1 + w] = (float)be;
        }
    }
}

// ---------------- kernel 2: build padded segment layout ----------------------
__global__ void build_kernel() {
    int t = threadIdx.x;
    for (int i = t; i < PADT; i += blockDim.x) g_perm[i] = -1;
    if (t == 0) {
        int off = 0, tile = 0;
        for (int e = 0; e < NEXP; e++) {
            g_padoff[e] = off;
            int nt = (g_counts[e] + BM - 1) / BM;
            for (int i = 0; i < nt; i++) g_tile_expert[tile++] = e;
            off += nt * BM;
        }
        g_ntiles = tile;
    }
}

// ---------------- kernel 3: scatter tokens into permutation ------------------
__global__ void scatter_kernel() {
    int t = blockIdx.x * blockDim.x + threadIdx.x;
    if (t < TOK) {
        int e = g_expert[t];
        int pos = atomicAdd(&g_counts2[e], 1);
        g_perm[g_padoff[e] + pos] = t;
    }
}

// ---------------- GEMM 1: H = relu(gather(X) @ W_in[e]) ----------------------
__global__ __launch_bounds__(256, 2)
void gemm1_kernel(const float* __restrict__ x, const float* __restrict__ w_in) {
    int tm = blockIdx.y; if (tm >= g_ntiles) return;
    int tn = blockIdx.x;
    int e  = g_tile_expert[tm];
    const float* Bg = w_in + (size_t)e * DDIM * FDIM + (size_t)tn * BN;

    __shared__ float As[BK][BM];
    __shared__ float Bs[BK][BN];

    int tid  = threadIdx.x;
    int arow = tid >> 1;
    int ak   = (tid & 1) * 4;
    int token = g_perm[tm * BM + arow];
    const float* Ag = (token >= 0) ? (x + (size_t)token * DDIM + ak) : nullptr;
    int bk = tid >> 5;
    int bn = (tid & 31) * 4;
    const float* Bgp = Bg + (size_t)bk * FDIM + bn;

    float acc[8][8];
#pragma unroll
    for (int i = 0; i < 8; i++)
#pragma unroll
        for (int j = 0; j < 8; j++) acc[i][j] = 0.f;

    int ty = (tid >> 4) * 8;
    int tx = (tid & 15) * 8;

    for (int k0 = 0; k0 < DDIM; k0 += BK) {
        float4 av = Ag ? *(const float4*)(Ag + k0) : make_float4(0.f, 0.f, 0.f, 0.f);
        As[ak + 0][arow] = av.x; As[ak + 1][arow] = av.y;
        As[ak + 2][arow] = av.z; As[ak + 3][arow] = av.w;
        float4 bv = *(const float4*)(Bgp + (size_t)k0 * FDIM);
        *(float4*)&Bs[bk][bn] = bv;
        __syncthreads();
#pragma unroll
        for (int k = 0; k < BK; k++) {
            float4 a0 = *(float4*)&As[k][ty], a1 = *(float4*)&As[k][ty + 4];
            float4 b0 = *(float4*)&Bs[k][tx], b1 = *(float4*)&Bs[k][tx + 4];
            float a[8] = {a0.x, a0.y, a0.z, a0.w, a1.x, a1.y, a1.z, a1.w};
            float b[8] = {b0.x, b0.y, b0.z, b0.w, b1.x, b1.y, b1.z, b1.w};
#pragma unroll
            for (int i = 0; i < 8; i++)
#pragma unroll
                for (int j = 0; j < 8; j++) acc[i][j] = fmaf(a[i], b[j], acc[i][j]);
        }
        __syncthreads();
    }

    float* Hp = g_hidden + (size_t)(tm * BM) * FDIM + (size_t)tn * BN;
#pragma unroll
    for (int i = 0; i < 8; i++) {
        float4 v0, v1;
        v0.x = fmaxf(acc[i][0], 0.f); v0.y = fmaxf(acc[i][1], 0.f);
        v0.z = fmaxf(acc[i][2], 0.f); v0.w = fmaxf(acc[i][3], 0.f);
        v1.x = fmaxf(acc[i][4], 0.f); v1.y = fmaxf(acc[i][5], 0.f);
        v1.z = fmaxf(acc[i][6], 0.f); v1.w = fmaxf(acc[i][7], 0.f);
        *(float4*)&Hp[(size_t)(ty + i) * FDIM + tx]     = v0;
        *(float4*)&Hp[(size_t)(ty + i) * FDIM + tx + 4] = v1;
    }
}

// ---------------- GEMM 2: out[token] = p * (H @ W_out[e]) --------------------
__global__ __launch_bounds__(256, 2)
void gemm2_kernel(const float* __restrict__ w_out, float* __restrict__ out) {
    int tm = blockIdx.y; if (tm >= g_ntiles) return;
    int tn = blockIdx.x;
    int e  = g_tile_expert[tm];
    const float* Bg = w_out + (size_t)e * FDIM * DDIM + (size_t)tn * BN;

    __shared__ float As[BK][BM];
    __shared__ float Bs[BK][BN];

    int tid  = threadIdx.x;
    int arow = tid >> 1;
    int ak   = (tid & 1) * 4;
    const float* Ag = g_hidden + (size_t)(tm * BM + arow) * FDIM + ak;
    int bk = tid >> 5;
    int bn = (tid & 31) * 4;
    const float* Bgp = Bg + (size_t)bk * DDIM + bn;

    float acc[8][8];
#pragma unroll
    for (int i = 0; i < 8; i++)
#pragma unroll
        for (int j = 0; j < 8; j++) acc[i][j] = 0.f;

    int ty = (tid >> 4) * 8;
    int tx = (tid & 15) * 8;

    for (int k0 = 0; k0 < FDIM; k0 += BK) {
        float4 av = *(const float4*)(Ag + k0);
        As[ak + 0][arow] = av.x; As[ak + 1][arow] = av.y;
        As[ak + 2][arow] = av.z; As[ak + 3][arow] = av.w;
        float4 bv = *(const float4*)(Bgp + (size_t)k0 * DDIM);
        *(float4*)&Bs[bk][bn] = bv;
        __syncthreads();
#pragma unroll
        for (int k = 0; k < BK; k++) {
            float4 a0 = *(float4*)&As[k][ty], a1 = *(float4*)&As[k][ty + 4];
            float4 b0 = *(float4*)&Bs[k][tx], b1 = *(float4*)&Bs[k][tx + 4];
            float a[8] = {a0.x, a0.y, a0.z, a0.w, a1.x, a1.y, a1.z, a1.w};
            float b[8] = {b0.x, b0.y, b0.z, b0.w, b1.x, b1.y, b1.z, b1.w};
#pragma unroll
            for (int i = 0; i < 8; i++)
#pragma unroll
                for (int j = 0; j < 8; j++) acc[i][j] = fmaf(a[i], b[j], acc[i][j]);
        }
        __syncthreads();
    }

#pragma unroll
    for (int i = 0; i < 8; i++) {
        int token = g_perm[tm * BM + ty + i];
        if (token < 0) continue;
        float p = g_top_prob[token];
        float4 v0, v1;
        v0.x = acc[i][0] * p; v0.y = acc[i][1] * p;
        v0.z = acc[i][2] * p; v0.w = acc[i][3] * p;
        v1.x = acc[i][4] * p; v1.y = acc[i][5] * p;
        v1.z = acc[i][6] * p; v1.w = acc[i][7] * p;
        float* op = out + (size_t)token * DDIM + (size_t)tn * BN + tx;
        *(float4*)&op[0] = v0;
        *(float4*)&op[4] = v1;
    }
}

// ---------------- launch ------------------------------------------------------
extern "C" void kernel_launch(void* const* d_in, const int* in_sizes, int n_in,
                              void* d_out, int out_size) {
    const float* x  = (const float*)d_in[0];   // hidden_states [B,S,D]
    const float* rw = (const float*)d_in[1];   // router_w [D,E]
    const float* wi = (const float*)d_in[2];   // w_in  [E,D,F]
    const float* wo = (const float*)d_in[3];   // w_out [E,F,D]
    float* out = (float*)d_out;

    int aux = ((size_t)out_size >= OUT1 + TOK) ? 1 : 0;

    reset_kernel<<<1, 32>>>();
    router_kernel<<<(TOK * 32 + 255) / 256, 256>>>(x, rw, out, aux);
    build_kernel<<<1, 256>>>();
    scatter_kernel<<<(TOK + 255) / 256, 256>>>();
    gemm1_kernel<<<dim3(FDIM / BN, MAXTILES), 256>>>(x, wi);
    gemm2_kernel<<<dim3(DDIM / BN, MAXTILES), 256>>>(wo, out);
}